// round 12
// baseline (speedup 1.0000x reference)
#include <cuda_runtime.h>
#include <cuda_bf16.h>
#include <math.h>
#include <stdint.h>

// Problem dims
#define TT   512
#define BB   128
#define II   512
#define HH   512
#define G4   2048
#define NBLK 128         // persistent blocks for recurrence
#define TBH  ((size_t)TT * BB * HH)

// ---------------------------------------------------------------------------
// Device scratch (allocation-free rule)
// ---------------------------------------------------------------------------
__device__ __nv_bfloat16 g_Xhi[(size_t)TT * BB * II];   // 64MB
__device__ __nv_bfloat16 g_Xlo[(size_t)TT * BB * II];   // 64MB
__device__ __nv_bfloat16 g_Whi[G4 * II];                // 2MB
__device__ __nv_bfloat16 g_Wlo[G4 * II];                // 2MB
__device__ float         g_bias[G4];
__device__ float         g_xg[(size_t)TT * G4 * BB];    // 512MB, layout [t][n][b]
__device__ __nv_bfloat16 g_Hhi[2][BB * HH];             // h (bf16), double-buffered
__device__ unsigned      g_syncg[128];                  // per-group barrier ctrs (use [gb*32])

// ---------------------------------------------------------------------------
// Helpers
// ---------------------------------------------------------------------------
__device__ __forceinline__ void split2(float x, uint32_t& h, uint32_t& l) {
    __nv_bfloat16 hb = __float2bfloat16_rn(x);
    float r = x - __bfloat162float(hb);
    __nv_bfloat16 lb = __float2bfloat16_rn(r);
    h = (uint32_t)__bfloat16_as_ushort(hb);
    l = (uint32_t)__bfloat16_as_ushort(lb);
}
__device__ __forceinline__ uint32_t smem_u32(const void* p) {
    return (uint32_t)__cvta_generic_to_shared(p);
}
__device__ __forceinline__ void ldmx4(uint32_t& r0, uint32_t& r1, uint32_t& r2, uint32_t& r3,
                                      uint32_t addr) {
    asm volatile("ldmatrix.sync.aligned.m8n8.x4.shared.b16 {%0,%1,%2,%3}, [%4];"
                 : "=r"(r0), "=r"(r1), "=r"(r2), "=r"(r3) : "r"(addr));
}
__device__ __forceinline__ void ldmx2(uint32_t& r0, uint32_t& r1, uint32_t addr) {
    asm volatile("ldmatrix.sync.aligned.m8n8.x2.shared.b16 {%0,%1}, [%2];"
                 : "=r"(r0), "=r"(r1) : "r"(addr));
}
__device__ __forceinline__ void mma_bf16(float* d, const uint32_t* a, const uint32_t* b) {
    asm volatile(
        "mma.sync.aligned.m16n8k16.row.col.f32.bf16.bf16.f32 "
        "{%0,%1,%2,%3}, {%4,%5,%6,%7}, {%8,%9}, {%0,%1,%2,%3};"
        : "+f"(d[0]), "+f"(d[1]), "+f"(d[2]), "+f"(d[3])
        : "r"(a[0]), "r"(a[1]), "r"(a[2]), "r"(a[3]), "r"(b[0]), "r"(b[1]));
}
// fast transcendentals (safe limits: clamp keeps e^2x finite; +/-1 exact tails)
__device__ __forceinline__ float fsigmoid(float x) {
    return 1.0f / (1.0f + __expf(-x));
}
__device__ __forceinline__ float ftanh(float x) {
    float e = __expf(fminf(2.0f * x, 80.0f));
    return (e - 1.0f) / (e + 1.0f);
}

// ---------------------------------------------------------------------------
// convert_init: split X and W_ih into bf16 hi/lo, build bias, zero barriers.
// ---------------------------------------------------------------------------
__global__ void convert_init(const float* __restrict__ X, const float* __restrict__ W,
                             const float* __restrict__ b1, const float* __restrict__ b2)
{
    size_t i0 = (size_t)blockIdx.x * blockDim.x + threadIdx.x;
    size_t stride = (size_t)gridDim.x * blockDim.x;
    const size_t NX4 = (size_t)TT * BB * II / 4;
    const size_t NW4 = (size_t)G4 * II / 4;

    for (size_t i = i0; i < NX4; i += stride) {
        float4 v = ((const float4*)X)[i];
        uint32_t h0, h1, h2, h3, l0, l1, l2, l3;
        split2(v.x, h0, l0); split2(v.y, h1, l1);
        split2(v.z, h2, l2); split2(v.w, h3, l3);
        ((uint2*)g_Xhi)[i] = make_uint2(h0 | (h1 << 16), h2 | (h3 << 16));
        ((uint2*)g_Xlo)[i] = make_uint2(l0 | (l1 << 16), l2 | (l3 << 16));
    }
    for (size_t i = i0; i < NW4; i += stride) {
        float4 v = ((const float4*)W)[i];
        uint32_t h0, h1, h2, h3, l0, l1, l2, l3;
        split2(v.x, h0, l0); split2(v.y, h1, l1);
        split2(v.z, h2, l2); split2(v.w, h3, l3);
        ((uint2*)g_Whi)[i] = make_uint2(h0 | (h1 << 16), h2 | (h3 << 16));
        ((uint2*)g_Wlo)[i] = make_uint2(l0 | (l1 << 16), l2 | (l3 << 16));
    }
    for (size_t i = i0; i < G4; i += stride) g_bias[i] = b1[i] + b2[i];
    for (size_t i = i0; i < 128; i += stride) g_syncg[i] = 0u;
}

// ---------------------------------------------------------------------------
// sgemm_bf16: g_xg[t][n][b] = sum_k X[t][b][k] * W_ih[n][k] + bias[n]
// (byte-identical to round 6..11 winner)
// ---------------------------------------------------------------------------
#define STG_PITCH 132   // floats; 528B row, 16B aligned, conflict-free

__global__ void __launch_bounds__(256) sgemm_bf16()
{
    __shared__ __align__(16) char SMEM[40960];
    __nv_bfloat16* Ah = (__nv_bfloat16*)(SMEM);
    __nv_bfloat16* Al = (__nv_bfloat16*)(SMEM + 10240);
    __nv_bfloat16* Bh = (__nv_bfloat16*)(SMEM + 20480);
    __nv_bfloat16* Bl = (__nv_bfloat16*)(SMEM + 30720);

    const int t    = threadIdx.x;
    const int lane = t & 31;
    const int w    = t >> 5;
    const int wm   = w >> 1;
    const int wn   = w & 1;
    const int tt   = blockIdx.y;
    const int m0   = tt * 128;
    const int n0   = blockIdx.x * 128;

    const int row0 = t >> 2;
    const int grp  = t & 3;
    size_t ao0 = (size_t)(m0 + row0) * II + grp * 8;
    size_t ao1 = ao0 + (size_t)64 * II;
    size_t bo0 = (size_t)(n0 + row0) * II + grp * 8;
    size_t bo1 = bo0 + (size_t)64 * II;
    const int s0 = row0 * 40 + grp * 8;
    const int s1 = s0 + 64 * 40;

    const uint32_t uAh = smem_u32(Ah), uAl = smem_u32(Al);
    const uint32_t uBh = smem_u32(Bh), uBl = smem_u32(Bl);
    const int a_r = lane & 15, a_c = (lane >> 4) << 3;
    const int b_r = lane & 7,  b_c = ((lane >> 3) & 1) << 3;

    float d[2][8][4] = {{{0.f}}};

    uint4 pAh0 = *(const uint4*)(g_Xhi + ao0);
    uint4 pAh1 = *(const uint4*)(g_Xhi + ao1);
    uint4 pAl0 = *(const uint4*)(g_Xlo + ao0);
    uint4 pAl1 = *(const uint4*)(g_Xlo + ao1);
    uint4 pBh0 = *(const uint4*)(g_Whi + bo0);
    uint4 pBh1 = *(const uint4*)(g_Whi + bo1);
    uint4 pBl0 = *(const uint4*)(g_Wlo + bo0);
    uint4 pBl1 = *(const uint4*)(g_Wlo + bo1);

    for (int it = 0; it < 16; ++it) {
        __syncthreads();
        *(uint4*)(Ah + s0) = pAh0; *(uint4*)(Ah + s1) = pAh1;
        *(uint4*)(Al + s0) = pAl0; *(uint4*)(Al + s1) = pAl1;
        *(uint4*)(Bh + s0) = pBh0; *(uint4*)(Bh + s1) = pBh1;
        *(uint4*)(Bl + s0) = pBl0; *(uint4*)(Bl + s1) = pBl1;
        __syncthreads();

        if (it != 15) {
            ao0 += 32; ao1 += 32; bo0 += 32; bo1 += 32;
            pAh0 = *(const uint4*)(g_Xhi + ao0);
            pAh1 = *(const uint4*)(g_Xhi + ao1);
            pAl0 = *(const uint4*)(g_Xlo + ao0);
            pAl1 = *(const uint4*)(g_Xlo + ao1);
            pBh0 = *(const uint4*)(g_Whi + bo0);
            pBh1 = *(const uint4*)(g_Whi + bo1);
            pBl0 = *(const uint4*)(g_Wlo + bo0);
            pBl1 = *(const uint4*)(g_Wlo + bo1);
        }

#pragma unroll
        for (int ks = 0; ks < 2; ++ks) {
            uint32_t ah[2][4], al[2][4];
#pragma unroll
            for (int mt = 0; mt < 2; ++mt) {
                uint32_t ra = uAh + (uint32_t)(((wm * 32 + mt * 16 + a_r) * 40 + ks * 16 + a_c) * 2);
                ldmx4(ah[mt][0], ah[mt][1], ah[mt][2], ah[mt][3], ra);
                uint32_t rl = uAl + (uint32_t)(((wm * 32 + mt * 16 + a_r) * 40 + ks * 16 + a_c) * 2);
                ldmx4(al[mt][0], al[mt][1], al[mt][2], al[mt][3], rl);
            }
#pragma unroll
            for (int nt = 0; nt < 8; ++nt) {
                uint32_t bh[2], bl[2];
                uint32_t rb = uBh + (uint32_t)(((wn * 64 + nt * 8 + b_r) * 40 + ks * 16 + b_c) * 2);
                ldmx2(bh[0], bh[1], rb);
                uint32_t rlb = uBl + (uint32_t)(((wn * 64 + nt * 8 + b_r) * 40 + ks * 16 + b_c) * 2);
                ldmx2(bl[0], bl[1], rlb);
#pragma unroll
                for (int mt = 0; mt < 2; ++mt) {
                    mma_bf16(d[mt][nt], ah[mt], bh);
                    mma_bf16(d[mt][nt], ah[mt], bl);
                    mma_bf16(d[mt][nt], al[mt], bh);
                }
            }
        }
    }

    // Epilogue: two halves of 64 n-cols; transpose via smem, coalesced store.
    float* staging = (float*)SMEM;
    const int gid = lane >> 2, tig = lane & 3;
#pragma unroll
    for (int nh = 0; nh < 2; ++nh) {
        __syncthreads();
        if (wn == nh) {
#pragma unroll
            for (int mt = 0; mt < 2; ++mt)
#pragma unroll
                for (int nt = 0; nt < 8; ++nt) {
                    int c = nt * 8 + 2 * tig;            // local col in half
                    int r = wm * 32 + mt * 16 + gid;     // batch row
                    staging[c * STG_PITCH + r]           = d[mt][nt][0];
                    staging[(c + 1) * STG_PITCH + r]     = d[mt][nt][1];
                    staging[c * STG_PITCH + r + 8]       = d[mt][nt][2];
                    staging[(c + 1) * STG_PITCH + r + 8] = d[mt][nt][3];
                }
        }
        __syncthreads();
#pragma unroll
        for (int j = 0; j < 8; ++j) {
            int idx = t + 256 * j;            // 2048 float4 = 64 cols x 32 segs
            int col = idx >> 5, seg = idx & 31;
            int n = n0 + nh * 64 + col;
            float bb = g_bias[n];
            const float* sp = &staging[col * STG_PITCH + seg * 4];
            float4 v = make_float4(sp[0] + bb, sp[1] + bb, sp[2] + bb, sp[3] + bb);
            *(float4*)&g_xg[((size_t)tt * G4 + n) * BB + seg * 4] = v;
        }
    }
}

// ---------------------------------------------------------------------------
// Persistent recurrent kernel — round-11 winner + TWO changes:
//  (1) split accumulators: even-kk -> d, odd-kk -> e, combined at the end.
//      4 independent HMMA chains per warp (was 2) — probes whether the mma
//      loop is latency-bound on the accumulator RAW chain.
//  (2) fast tanh via __expf (clamped) in the elementwise phase.
// ---------------------------------------------------------------------------
#define RW_PITCH 520
#define RS_WSH 0
#define RS_WSL 66560
#define RS_HS  133120
#define RS_CS  166400
#define RS_HST 174848
#define RS_TOT 177152

__global__ void __launch_bounds__(256, 1) lstm_rec(const float* __restrict__ Whh,
                                                   float* __restrict__ out,
                                                   int tail)
{
    extern __shared__ __align__(16) char rsm[];
    __nv_bfloat16* Wsh = (__nv_bfloat16*)(rsm + RS_WSH);
    __nv_bfloat16* Wsl = (__nv_bfloat16*)(rsm + RS_WSL);
    float*         Cs  = (float*)(rsm + RS_CS);      // [64 col][33] transposed
    float*      hstage = (float*)(rsm + RS_HST);     // [32 b][17]
    const uint32_t uSM = smem_u32(rsm);

    const int tid  = threadIdx.x;
    const int lane = tid & 31;
    const int w    = tid >> 5;
    const int gid  = lane >> 2;
    const int tig  = lane & 3;
    const int gh   = blockIdx.x & 31;   // h-col group
    const int gb   = blockIdx.x >> 5;   // batch group (independent recurrence)
    const int hc0  = gh * 16;
    const int b0   = gb * 32;
    volatile unsigned* mybar = &g_syncg[gb * 32];

    // Load + split W_hh slice: Ws[j][k] = Whh[(j>>4)*512 + hc0 + (j&15)][k]
    for (int idx = tid; idx < 64 * 512; idx += 256) {
        int j = idx >> 9, k = idx & 511;
        int n = (j >> 4) * 512 + hc0 + (j & 15);
        float v = Whh[(size_t)n * HH + k];
        uint32_t hb, lb;
        split2(v, hb, lb);
        Wsh[j * RW_PITCH + k] = __ushort_as_bfloat16((unsigned short)hb);
        Wsl[j * RW_PITCH + k] = __ushort_as_bfloat16((unsigned short)lb);
    }
    __syncthreads();

    const int wm  = w & 1;              // m-tile (16 batches)
    const int wn  = w >> 1;             // n-group (16 gate cols)
    const int a_r = lane & 15, a_c = (lane >> 4) << 3;
    // B ldmatrix.x4 lane mapping: m0=nt0/k0-7, m1=nt0/k8-15, m2=nt1/k0-7, m3=nt1/k8-15
    const int b_nrow = wn * 16 + ((lane >> 4) << 3) + (lane & 7);
    const int b_koff = ((lane >> 3) & 1) << 3;
    const int e_b = tid & 31;           // local batch
    const int e_r = tid >> 5;           // ci base (handles ci = e_r, e_r+8)
    float creg[2] = {0.f, 0.f};

    // prologue: prefetch gates for t=0
    float xv[2][4];
#pragma unroll
    for (int pi = 0; pi < 2; ++pi) {
        int ci = e_r + pi * 8;
#pragma unroll
        for (int q = 0; q < 4; ++q)
            xv[pi][q] = g_xg[(size_t)(q * 512 + hc0 + ci) * BB + b0 + e_b];
    }

    for (int t = 0; t < TT; ++t) {
        if (t > 0) {
            // load h slice: 32 rows x 512 bf16 = 2048 uint4, one shot
            const __nv_bfloat16* srcH = g_Hhi[(t - 1) & 1];
#pragma unroll
            for (int j = 0; j < 8; ++j) {
                int idx = tid + 256 * j;
                int row = idx >> 6, seg = idx & 63;
                *(uint4*)(rsm + RS_HS + (row * RW_PITCH + seg * 8) * 2) =
                    *(const uint4*)(srcH + (size_t)(b0 + row) * HH + seg * 8);
            }
            __syncthreads();

            float d[2][4] = {{0.f, 0.f, 0.f, 0.f}};
            float e[2][4] = {{0.f, 0.f, 0.f, 0.f}};
#pragma unroll 4
            for (int kk = 0; kk < 32; kk += 2) {
                // even kk -> d
                {
                    const int kb = kk * 16;
                    uint32_t ah[4];
                    uint32_t aoff = (uint32_t)(((wm * 16 + a_r) * RW_PITCH + kb + a_c) * 2);
                    ldmx4(ah[0], ah[1], ah[2], ah[3], uSM + RS_HS + aoff);
                    uint32_t boff = (uint32_t)((b_nrow * RW_PITCH + kb + b_koff) * 2);
                    uint32_t bh4[4], bl4[4];
                    ldmx4(bh4[0], bh4[1], bh4[2], bh4[3], uSM + RS_WSH + boff);
                    ldmx4(bl4[0], bl4[1], bl4[2], bl4[3], uSM + RS_WSL + boff);
                    mma_bf16(d[0], ah, bh4 + 0);
                    mma_bf16(d[0], ah, bl4 + 0);
                    mma_bf16(d[1], ah, bh4 + 2);
                    mma_bf16(d[1], ah, bl4 + 2);
                }
                // odd kk+1 -> e (independent accumulator chain)
                {
                    const int kb = (kk + 1) * 16;
                    uint32_t ah[4];
                    uint32_t aoff = (uint32_t)(((wm * 16 + a_r) * RW_PITCH + kb + a_c) * 2);
                    ldmx4(ah[0], ah[1], ah[2], ah[3], uSM + RS_HS + aoff);
                    uint32_t boff = (uint32_t)((b_nrow * RW_PITCH + kb + b_koff) * 2);
                    uint32_t bh4[4], bl4[4];
                    ldmx4(bh4[0], bh4[1], bh4[2], bh4[3], uSM + RS_WSH + boff);
                    ldmx4(bl4[0], bl4[1], bl4[2], bl4[3], uSM + RS_WSL + boff);
                    mma_bf16(e[0], ah, bh4 + 0);
                    mma_bf16(e[0], ah, bl4 + 0);
                    mma_bf16(e[1], ah, bh4 + 2);
                    mma_bf16(e[1], ah, bl4 + 2);
                }
            }
#pragma unroll
            for (int nt = 0; nt < 2; ++nt)
#pragma unroll
                for (int i = 0; i < 4; ++i) d[nt][i] += e[nt][i];

            // dump C fragments transposed: Cs[col][b]
            const int arow = wm * 16 + gid;
#pragma unroll
            for (int nt = 0; nt < 2; ++nt) {
                int c0 = wn * 16 + nt * 8 + 2 * tig;
                Cs[c0 * 33 + arow]           = d[nt][0];
                Cs[(c0 + 1) * 33 + arow]     = d[nt][1];
                Cs[c0 * 33 + arow + 8]       = d[nt][2];
                Cs[(c0 + 1) * 33 + arow + 8] = d[nt][3];
            }
        }
        __syncthreads();

        // Fused fp32 LSTM elementwise -> h to smem stage
#pragma unroll
        for (int pi = 0; pi < 2; ++pi) {
            int ci = e_r + pi * 8;
            float gate[4];
#pragma unroll
            for (int q = 0; q < 4; ++q) {
                float s = (t > 0) ? Cs[(q * 16 + ci) * 33 + e_b] : 0.f;
                gate[q] = s + xv[pi][q];
            }
            float ig = fsigmoid(gate[0]);
            float fg = fsigmoid(gate[1]);
            float gg = ftanh(gate[2]);
            float og = fsigmoid(gate[3]);
            float cn = fg * creg[pi] + ig * gg;
            creg[pi] = cn;
            hstage[e_b * 17 + ci] = og * ftanh(cn);
        }
        __syncthreads();

        // coalesced h writes: float4 out + uint2 bf16 h (4 cols per thread)
        if (tid < 128) {
            int bl_ = tid >> 2, qd = tid & 3;
            const float* hp = &hstage[bl_ * 17 + qd * 4];
            float h0 = hp[0], h1 = hp[1], h2 = hp[2], h3 = hp[3];
            *(float4*)(out + (size_t)t * BB * HH + (size_t)(b0 + bl_) * HH + hc0 + qd * 4) =
                make_float4(h0, h1, h2, h3);
            uint32_t p0 = (uint32_t)__bfloat16_as_ushort(__float2bfloat16_rn(h0)) |
                          ((uint32_t)__bfloat16_as_ushort(__float2bfloat16_rn(h1)) << 16);
            uint32_t p1 = (uint32_t)__bfloat16_as_ushort(__float2bfloat16_rn(h2)) |
                          ((uint32_t)__bfloat16_as_ushort(__float2bfloat16_rn(h3)) << 16);
            *(uint2*)(g_Hhi[t & 1] + (size_t)(b0 + bl_) * HH + hc0 + qd * 4) =
                make_uint2(p0, p1);
        }

        // prefetch next step's gates BEFORE the barrier (hidden in the wait)
        if (t + 1 < TT) {
            const float* xgn = g_xg + (size_t)(t + 1) * G4 * BB;
#pragma unroll
            for (int pi = 0; pi < 2; ++pi) {
                int ci = e_r + pi * 8;
#pragma unroll
                for (int q = 0; q < 4; ++q)
                    xv[pi][q] = xgn[(size_t)(q * 512 + hc0 + ci) * BB + b0 + e_b];
            }
        }

        // per-group barrier (only the 32 same-gb blocks interact)
        __syncthreads();
        if (tid == 0) {
            __threadfence();
            atomicAdd((unsigned*)mybar, 1u);
            unsigned target = (unsigned)(t + 1) * 32u;
            while (*mybar < target) { }
            __threadfence();
        }
        __syncthreads();
    }

    // tail: hT copy + cT from registers
    if (tail) {
#pragma unroll
        for (int pi = 0; pi < 2; ++pi) {
            int ci = e_r + pi * 8;
            size_t idx = (size_t)(b0 + e_b) * HH + hc0 + ci;
            out[TBH + idx]           = out[(size_t)(TT - 1) * BB * HH + idx];
            out[TBH + BB * HH + idx] = creg[pi];
        }
    }
}

// ---------------------------------------------------------------------------
extern "C" void kernel_launch(void* const* d_in, const int* in_sizes, int n_in,
                              void* d_out, int out_size)
{
    const float* input = (const float*)d_in[0];
    /* d_in[1] = time, unused by the base cell */
    const float* W_ih  = (const float*)d_in[2];
    const float* W_hh  = (const float*)d_in[3];
    const float* b_ih  = (const float*)d_in[4];
    const float* b_hh  = (const float*)d_in[5];
    float* out = (float*)d_out;

    int tail = ((size_t)out_size >= TBH + 2ull * BB * HH) ? 1 : 0;

    convert_init<<<2048, 256>>>(input, W_ih, b_ih, b_hh);
    sgemm_bf16<<<dim3(16, 512), 256>>>();

    cudaFuncSetAttribute(lstm_rec, cudaFuncAttributeMaxDynamicSharedMemorySize, RS_TOT);
    lstm_rec<<<NBLK, 256, RS_TOT>>>(W_hh, out, tail);
}

// round 13
// speedup vs baseline: 1.1799x; 1.1799x over previous
#include <cuda_runtime.h>
#include <cuda_fp16.h>
#include <math.h>
#include <stdint.h>

// Problem dims
#define TT   512
#define BB   128
#define II   512
#define HH   512
#define G4   2048
#define NBLK 128         // persistent blocks for recurrence
#define TBH  ((size_t)TT * BB * HH)

// ---------------------------------------------------------------------------
// Device scratch (allocation-free rule)
// ---------------------------------------------------------------------------
__device__ __half    g_Xf[(size_t)TT * BB * II];    // 64MB (f16 x, single stream)
__device__ __half    g_Whi[G4 * II];                // 2MB  (f16 W_ih hi)
__device__ __half    g_Wlo[G4 * II];                // 2MB  (f16 W_ih lo)
__device__ float     g_bias[G4];
__device__ float     g_xg[(size_t)TT * G4 * BB];    // 512MB, layout [t][n][b]
__device__ __half    g_Hf[2][BB * HH];              // h (f16), double-buffered
__device__ unsigned  g_syncg[128];                  // per-group barrier ctrs (use [gb*32])

// ---------------------------------------------------------------------------
// Helpers
// ---------------------------------------------------------------------------
__device__ __forceinline__ void split2h(float x, uint32_t& h, uint32_t& l) {
    __half hb = __float2half_rn(x);
    float r = x - __half2float(hb);
    __half lb = __float2half_rn(r);
    h = (uint32_t)__half_as_ushort(hb);
    l = (uint32_t)__half_as_ushort(lb);
}
__device__ __forceinline__ uint32_t smem_u32(const void* p) {
    return (uint32_t)__cvta_generic_to_shared(p);
}
__device__ __forceinline__ void ldmx4(uint32_t& r0, uint32_t& r1, uint32_t& r2, uint32_t& r3,
                                      uint32_t addr) {
    asm volatile("ldmatrix.sync.aligned.m8n8.x4.shared.b16 {%0,%1,%2,%3}, [%4];"
                 : "=r"(r0), "=r"(r1), "=r"(r2), "=r"(r3) : "r"(addr));
}
__device__ __forceinline__ void ldmx2(uint32_t& r0, uint32_t& r1, uint32_t addr) {
    asm volatile("ldmatrix.sync.aligned.m8n8.x2.shared.b16 {%0,%1}, [%2];"
                 : "=r"(r0), "=r"(r1) : "r"(addr));
}
__device__ __forceinline__ void mma_f16(float* d, const uint32_t* a, const uint32_t* b) {
    asm volatile(
        "mma.sync.aligned.m16n8k16.row.col.f32.f16.f16.f32 "
        "{%0,%1,%2,%3}, {%4,%5,%6,%7}, {%8,%9}, {%0,%1,%2,%3};"
        : "+f"(d[0]), "+f"(d[1]), "+f"(d[2]), "+f"(d[3])
        : "r"(a[0]), "r"(a[1]), "r"(a[2]), "r"(a[3]), "r"(b[0]), "r"(b[1]));
}

// ---------------------------------------------------------------------------
// convert_init: x -> f16, W_ih -> f16 hi/lo, build bias, zero barriers.
// ---------------------------------------------------------------------------
__global__ void convert_init(const float* __restrict__ X, const float* __restrict__ W,
                             const float* __restrict__ b1, const float* __restrict__ b2)
{
    size_t i0 = (size_t)blockIdx.x * blockDim.x + threadIdx.x;
    size_t stride = (size_t)gridDim.x * blockDim.x;
    const size_t NX4 = (size_t)TT * BB * II / 4;
    const size_t NW4 = (size_t)G4 * II / 4;

    for (size_t i = i0; i < NX4; i += stride) {
        float4 v = ((const float4*)X)[i];
        uint32_t a = (uint32_t)__half_as_ushort(__float2half_rn(v.x)) |
                     ((uint32_t)__half_as_ushort(__float2half_rn(v.y)) << 16);
        uint32_t b = (uint32_t)__half_as_ushort(__float2half_rn(v.z)) |
                     ((uint32_t)__half_as_ushort(__float2half_rn(v.w)) << 16);
        ((uint2*)g_Xf)[i] = make_uint2(a, b);
    }
    for (size_t i = i0; i < NW4; i += stride) {
        float4 v = ((const float4*)W)[i];
        uint32_t h0, h1, h2, h3, l0, l1, l2, l3;
        split2h(v.x, h0, l0); split2h(v.y, h1, l1);
        split2h(v.z, h2, l2); split2h(v.w, h3, l3);
        ((uint2*)g_Whi)[i] = make_uint2(h0 | (h1 << 16), h2 | (h3 << 16));
        ((uint2*)g_Wlo)[i] = make_uint2(l0 | (l1 << 16), l2 | (l3 << 16));
    }
    for (size_t i = i0; i < G4; i += stride) g_bias[i] = b1[i] + b2[i];
    for (size_t i = i0; i < 128; i += stride) g_syncg[i] = 0u;
}

// ---------------------------------------------------------------------------
// sgemm_f16: g_xg[t][n][b] = sum_k X[t][b][k] * W_ih[n][k] + bias[n]
// 2-pass f16: x_f16 * (W_hi + W_lo). Structure identical to the validated
// round-6..11 mainloop with the Al stream removed.
// ---------------------------------------------------------------------------
#define STG_PITCH 132   // floats; 528B row, 16B aligned, conflict-free

__global__ void __launch_bounds__(256) sgemm_f16()
{
    __shared__ __align__(16) char SMEM[33792];
    __half* Ah = (__half*)(SMEM);
    __half* Bh = (__half*)(SMEM + 10240);
    __half* Bl = (__half*)(SMEM + 20480);

    const int t    = threadIdx.x;
    const int lane = t & 31;
    const int w    = t >> 5;
    const int wm   = w >> 1;
    const int wn   = w & 1;
    const int tt   = blockIdx.y;
    const int m0   = tt * 128;
    const int n0   = blockIdx.x * 128;

    const int row0 = t >> 2;
    const int grp  = t & 3;
    size_t ao0 = (size_t)(m0 + row0) * II + grp * 8;
    size_t ao1 = ao0 + (size_t)64 * II;
    size_t bo0 = (size_t)(n0 + row0) * II + grp * 8;
    size_t bo1 = bo0 + (size_t)64 * II;
    const int s0 = row0 * 40 + grp * 8;
    const int s1 = s0 + 64 * 40;

    const uint32_t uAh = smem_u32(Ah);
    const uint32_t uBh = smem_u32(Bh), uBl = smem_u32(Bl);
    const int a_r = lane & 15, a_c = (lane >> 4) << 3;
    const int b_r = lane & 7,  b_c = ((lane >> 3) & 1) << 3;

    float d[2][8][4] = {{{0.f}}};

    uint4 pAh0 = *(const uint4*)(g_Xf + ao0);
    uint4 pAh1 = *(const uint4*)(g_Xf + ao1);
    uint4 pBh0 = *(const uint4*)(g_Whi + bo0);
    uint4 pBh1 = *(const uint4*)(g_Whi + bo1);
    uint4 pBl0 = *(const uint4*)(g_Wlo + bo0);
    uint4 pBl1 = *(const uint4*)(g_Wlo + bo1);

    for (int it = 0; it < 16; ++it) {
        __syncthreads();
        *(uint4*)(Ah + s0) = pAh0; *(uint4*)(Ah + s1) = pAh1;
        *(uint4*)(Bh + s0) = pBh0; *(uint4*)(Bh + s1) = pBh1;
        *(uint4*)(Bl + s0) = pBl0; *(uint4*)(Bl + s1) = pBl1;
        __syncthreads();

        if (it != 15) {
            ao0 += 32; ao1 += 32; bo0 += 32; bo1 += 32;
            pAh0 = *(const uint4*)(g_Xf + ao0);
            pAh1 = *(const uint4*)(g_Xf + ao1);
            pBh0 = *(const uint4*)(g_Whi + bo0);
            pBh1 = *(const uint4*)(g_Whi + bo1);
            pBl0 = *(const uint4*)(g_Wlo + bo0);
            pBl1 = *(const uint4*)(g_Wlo + bo1);
        }

#pragma unroll
        for (int ks = 0; ks < 2; ++ks) {
            uint32_t ah[2][4];
#pragma unroll
            for (int mt = 0; mt < 2; ++mt) {
                uint32_t ra = uAh + (uint32_t)(((wm * 32 + mt * 16 + a_r) * 40 + ks * 16 + a_c) * 2);
                ldmx4(ah[mt][0], ah[mt][1], ah[mt][2], ah[mt][3], ra);
            }
#pragma unroll
            for (int nt = 0; nt < 8; ++nt) {
                uint32_t bh[2], bl[2];
                uint32_t rb = uBh + (uint32_t)(((wn * 64 + nt * 8 + b_r) * 40 + ks * 16 + b_c) * 2);
                ldmx2(bh[0], bh[1], rb);
                uint32_t rlb = uBl + (uint32_t)(((wn * 64 + nt * 8 + b_r) * 40 + ks * 16 + b_c) * 2);
                ldmx2(bl[0], bl[1], rlb);
#pragma unroll
                for (int mt = 0; mt < 2; ++mt) {
                    mma_f16(d[mt][nt], ah[mt], bh);
                    mma_f16(d[mt][nt], ah[mt], bl);
                }
            }
        }
    }

    // Epilogue: two halves of 64 n-cols; transpose via smem, coalesced store.
    float* staging = (float*)SMEM;
    const int gid = lane >> 2, tig = lane & 3;
#pragma unroll
    for (int nh = 0; nh < 2; ++nh) {
        __syncthreads();
        if (wn == nh) {
#pragma unroll
            for (int mt = 0; mt < 2; ++mt)
#pragma unroll
                for (int nt = 0; nt < 8; ++nt) {
                    int c = nt * 8 + 2 * tig;            // local col in half
                    int r = wm * 32 + mt * 16 + gid;     // batch row
                    staging[c * STG_PITCH + r]           = d[mt][nt][0];
                    staging[(c + 1) * STG_PITCH + r]     = d[mt][nt][1];
                    staging[c * STG_PITCH + r + 8]       = d[mt][nt][2];
                    staging[(c + 1) * STG_PITCH + r + 8] = d[mt][nt][3];
                }
        }
        __syncthreads();
#pragma unroll
        for (int j = 0; j < 8; ++j) {
            int idx = t + 256 * j;            // 2048 float4 = 64 cols x 32 segs
            int col = idx >> 5, seg = idx & 31;
            int n = n0 + nh * 64 + col;
            float bb = g_bias[n];
            const float* sp = &staging[col * STG_PITCH + seg * 4];
            float4 v = make_float4(sp[0] + bb, sp[1] + bb, sp[2] + bb, sp[3] + bb);
            *(float4*)&g_xg[((size_t)tt * G4 + n) * BB + seg * 4] = v;
        }
    }
}

// ---------------------------------------------------------------------------
// Persistent recurrent kernel — EXACT round-11 structure (3907us winner),
// with only the datatype switched bf16 -> f16 (h single f16 stream, W_hh
// split f16 hi/lo, mma.f16). Same instruction counts, better precision.
// ---------------------------------------------------------------------------
#define RW_PITCH 520
#define RS_WSH 0
#define RS_WSL 66560
#define RS_HS  133120
#define RS_CS  166400
#define RS_HST 174848
#define RS_TOT 177152

__global__ void __launch_bounds__(256, 1) lstm_rec(const float* __restrict__ Whh,
                                                   float* __restrict__ out,
                                                   int tail)
{
    extern __shared__ __align__(16) char rsm[];
    __half* Wsh = (__half*)(rsm + RS_WSH);
    __half* Wsl = (__half*)(rsm + RS_WSL);
    float*  Cs  = (float*)(rsm + RS_CS);      // [64 col][33] transposed
    float* hstage = (float*)(rsm + RS_HST);   // [32 b][17]
    const uint32_t uSM = smem_u32(rsm);

    const int tid  = threadIdx.x;
    const int lane = tid & 31;
    const int w    = tid >> 5;
    const int gid  = lane >> 2;
    const int tig  = lane & 3;
    const int gh   = blockIdx.x & 31;   // h-col group
    const int gb   = blockIdx.x >> 5;   // batch group (independent recurrence)
    const int hc0  = gh * 16;
    const int b0   = gb * 32;
    volatile unsigned* mybar = &g_syncg[gb * 32];

    // Load + split W_hh slice (f16 hi/lo): Ws[j][k] = Whh[(j>>4)*512+hc0+(j&15)][k]
    for (int idx = tid; idx < 64 * 512; idx += 256) {
        int j = idx >> 9, k = idx & 511;
        int n = (j >> 4) * 512 + hc0 + (j & 15);
        float v = Whh[(size_t)n * HH + k];
        uint32_t hb, lb;
        split2h(v, hb, lb);
        Wsh[j * RW_PITCH + k] = __ushort_as_half((unsigned short)hb);
        Wsl[j * RW_PITCH + k] = __ushort_as_half((unsigned short)lb);
    }
    __syncthreads();

    const int wm  = w & 1;              // m-tile (16 batches)
    const int wn  = w >> 1;             // n-group (16 gate cols)
    const int a_r = lane & 15, a_c = (lane >> 4) << 3;
    // B ldmatrix.x4 lane mapping: m0=nt0/k0-7, m1=nt0/k8-15, m2=nt1/k0-7, m3=nt1/k8-15
    const int b_nrow = wn * 16 + ((lane >> 4) << 3) + (lane & 7);
    const int b_koff = ((lane >> 3) & 1) << 3;
    const int e_b = tid & 31;           // local batch
    const int e_r = tid >> 5;           // ci base (handles ci = e_r, e_r+8)
    float creg[2] = {0.f, 0.f};

    // prologue: prefetch gates for t=0
    float xv[2][4];
#pragma unroll
    for (int pi = 0; pi < 2; ++pi) {
        int ci = e_r + pi * 8;
#pragma unroll
        for (int q = 0; q < 4; ++q)
            xv[pi][q] = g_xg[(size_t)(q * 512 + hc0 + ci) * BB + b0 + e_b];
    }

    for (int t = 0; t < TT; ++t) {
        if (t > 0) {
            // load h slice: 32 rows x 512 f16 = 2048 uint4, one shot
            const __half* srcH = g_Hf[(t - 1) & 1];
#pragma unroll
            for (int j = 0; j < 8; ++j) {
                int idx = tid + 256 * j;
                int row = idx >> 6, seg = idx & 63;
                *(uint4*)(rsm + RS_HS + (row * RW_PITCH + seg * 8) * 2) =
                    *(const uint4*)(srcH + (size_t)(b0 + row) * HH + seg * 8);
            }
            __syncthreads();

            float d[2][4] = {{0.f, 0.f, 0.f, 0.f}};
#pragma unroll 4
            for (int kk = 0; kk < 32; ++kk) {
                const int kb = kk * 16;
                uint32_t ah[4];
                uint32_t aoff = (uint32_t)(((wm * 16 + a_r) * RW_PITCH + kb + a_c) * 2);
                ldmx4(ah[0], ah[1], ah[2], ah[3], uSM + RS_HS + aoff);

                uint32_t boff = (uint32_t)((b_nrow * RW_PITCH + kb + b_koff) * 2);
                uint32_t bh4[4], bl4[4];
                ldmx4(bh4[0], bh4[1], bh4[2], bh4[3], uSM + RS_WSH + boff);
                ldmx4(bl4[0], bl4[1], bl4[2], bl4[3], uSM + RS_WSL + boff);
                mma_f16(d[0], ah, bh4 + 0);
                mma_f16(d[0], ah, bl4 + 0);
                mma_f16(d[1], ah, bh4 + 2);
                mma_f16(d[1], ah, bl4 + 2);
            }

            // dump C fragments transposed: Cs[col][b]
            const int arow = wm * 16 + gid;
#pragma unroll
            for (int nt = 0; nt < 2; ++nt) {
                int c0 = wn * 16 + nt * 8 + 2 * tig;
                Cs[c0 * 33 + arow]           = d[nt][0];
                Cs[(c0 + 1) * 33 + arow]     = d[nt][1];
                Cs[c0 * 33 + arow + 8]       = d[nt][2];
                Cs[(c0 + 1) * 33 + arow + 8] = d[nt][3];
            }
        }
        __syncthreads();

        // Fused fp32 LSTM elementwise -> h to smem stage
#pragma unroll
        for (int pi = 0; pi < 2; ++pi) {
            int ci = e_r + pi * 8;
            float gate[4];
#pragma unroll
            for (int q = 0; q < 4; ++q) {
                float s = (t > 0) ? Cs[(q * 16 + ci) * 33 + e_b] : 0.f;
                gate[q] = s + xv[pi][q];
            }
            float ig = 1.0f / (1.0f + __expf(-gate[0]));
            float fg = 1.0f / (1.0f + __expf(-gate[1]));
            float gg = tanhf(gate[2]);
            float og = 1.0f / (1.0f + __expf(-gate[3]));
            float cn = fg * creg[pi] + ig * gg;
            creg[pi] = cn;
            hstage[e_b * 17 + ci] = og * tanhf(cn);
        }
        __syncthreads();

        // coalesced h writes: float4 out + uint2 f16 h (4 cols per thread)
        if (tid < 128) {
            int bl_ = tid >> 2, qd = tid & 3;
            const float* hp = &hstage[bl_ * 17 + qd * 4];
            float h0 = hp[0], h1 = hp[1], h2 = hp[2], h3 = hp[3];
            *(float4*)(out + (size_t)t * BB * HH + (size_t)(b0 + bl_) * HH + hc0 + qd * 4) =
                make_float4(h0, h1, h2, h3);
            uint32_t p0 = (uint32_t)__half_as_ushort(__float2half_rn(h0)) |
                          ((uint32_t)__half_as_ushort(__float2half_rn(h1)) << 16);
            uint32_t p1 = (uint32_t)__half_as_ushort(__float2half_rn(h2)) |
                          ((uint32_t)__half_as_ushort(__float2half_rn(h3)) << 16);
            *(uint2*)(g_Hf[t & 1] + (size_t)(b0 + bl_) * HH + hc0 + qd * 4) =
                make_uint2(p0, p1);
        }

        // prefetch next step's gates BEFORE the barrier (hidden in the wait)
        if (t + 1 < TT) {
            const float* xgn = g_xg + (size_t)(t + 1) * G4 * BB;
#pragma unroll
            for (int pi = 0; pi < 2; ++pi) {
                int ci = e_r + pi * 8;
#pragma unroll
                for (int q = 0; q < 4; ++q)
                    xv[pi][q] = xgn[(size_t)(q * 512 + hc0 + ci) * BB + b0 + e_b];
            }
        }

        // per-group barrier (only the 32 same-gb blocks interact)
        __syncthreads();
        if (tid == 0) {
            __threadfence();
            atomicAdd((unsigned*)mybar, 1u);
            unsigned target = (unsigned)(t + 1) * 32u;
            while (*mybar < target) { }
            __threadfence();
        }
        __syncthreads();
    }

    // tail: hT copy + cT from registers
    if (tail) {
#pragma unroll
        for (int pi = 0; pi < 2; ++pi) {
            int ci = e_r + pi * 8;
            size_t idx = (size_t)(b0 + e_b) * HH + hc0 + ci;
            out[TBH + idx]           = out[(size_t)(TT - 1) * BB * HH + idx];
            out[TBH + BB * HH + idx] = creg[pi];
        }
    }
}

// ---------------------------------------------------------------------------
extern "C" void kernel_launch(void* const* d_in, const int* in_sizes, int n_in,
                              void* d_out, int out_size)
{
    const float* input = (const float*)d_in[0];
    /* d_in[1] = time, unused by the base cell */
    const float* W_ih  = (const float*)d_in[2];
    const float* W_hh  = (const float*)d_in[3];
    const float* b_ih  = (const float*)d_in[4];
    const float* b_hh  = (const float*)d_in[5];
    float* out = (float*)d_out;

    int tail = ((size_t)out_size >= TBH + 2ull * BB * HH) ? 1 : 0;

    convert_init<<<2048, 256>>>(input, W_ih, b_ih, b_hh);
    sgemm_f16<<<dim3(16, 512), 256>>>();

    cudaFuncSetAttribute(lstm_rec, cudaFuncAttributeMaxDynamicSharedMemorySize, RS_TOT);
    lstm_rec<<<NBLK, 256, RS_TOT>>>(W_hh, out, tail);
}

// round 14
// speedup vs baseline: 1.4410x; 1.2214x over previous
#include <cuda_runtime.h>
#include <cuda_fp16.h>
#include <math.h>
#include <stdint.h>

// Problem dims
#define TT   512
#define BB   128
#define II   512
#define HH   512
#define G4   2048
#define NBLK 128         // persistent blocks for recurrence
#define TBH  ((size_t)TT * BB * HH)

// ---------------------------------------------------------------------------
// Device scratch (allocation-free rule)
// ---------------------------------------------------------------------------
__device__ __half    g_Xf[(size_t)TT * BB * II];    // 64MB (f16 x)
__device__ __half    g_Wf[G4 * II];                 // 2MB  (f16 W_ih)
__device__ float     g_bias[G4];
__device__ float     g_xg[(size_t)TT * G4 * BB];    // 512MB, layout [t][n][b]
__device__ __half    g_Hf[2][BB * HH];              // h (f16), double-buffered
__device__ unsigned  g_syncg[128];                  // per-group barrier ctrs (use [gb*32])

// ---------------------------------------------------------------------------
// Helpers
// ---------------------------------------------------------------------------
__device__ __forceinline__ uint32_t smem_u32(const void* p) {
    return (uint32_t)__cvta_generic_to_shared(p);
}
__device__ __forceinline__ void ldmx4(uint32_t& r0, uint32_t& r1, uint32_t& r2, uint32_t& r3,
                                      uint32_t addr) {
    asm volatile("ldmatrix.sync.aligned.m8n8.x4.shared.b16 {%0,%1,%2,%3}, [%4];"
                 : "=r"(r0), "=r"(r1), "=r"(r2), "=r"(r3) : "r"(addr));
}
__device__ __forceinline__ void ldmx2(uint32_t& r0, uint32_t& r1, uint32_t addr) {
    asm volatile("ldmatrix.sync.aligned.m8n8.x2.shared.b16 {%0,%1}, [%2];"
                 : "=r"(r0), "=r"(r1) : "r"(addr));
}
__device__ __forceinline__ void mma_f16(float* d, const uint32_t* a, const uint32_t* b) {
    asm volatile(
        "mma.sync.aligned.m16n8k16.row.col.f32.f16.f16.f32 "
        "{%0,%1,%2,%3}, {%4,%5,%6,%7}, {%8,%9}, {%0,%1,%2,%3};"
        : "+f"(d[0]), "+f"(d[1]), "+f"(d[2]), "+f"(d[3])
        : "r"(a[0]), "r"(a[1]), "r"(a[2]), "r"(a[3]), "r"(b[0]), "r"(b[1]));
}

// ---------------------------------------------------------------------------
// convert_init: x -> f16, W_ih -> f16, build bias, zero barriers.
// ---------------------------------------------------------------------------
__global__ void convert_init(const float* __restrict__ X, const float* __restrict__ W,
                             const float* __restrict__ b1, const float* __restrict__ b2)
{
    size_t i0 = (size_t)blockIdx.x * blockDim.x + threadIdx.x;
    size_t stride = (size_t)gridDim.x * blockDim.x;
    const size_t NX4 = (size_t)TT * BB * II / 4;
    const size_t NW4 = (size_t)G4 * II / 4;

    for (size_t i = i0; i < NX4; i += stride) {
        float4 v = ((const float4*)X)[i];
        uint32_t a = (uint32_t)__half_as_ushort(__float2half_rn(v.x)) |
                     ((uint32_t)__half_as_ushort(__float2half_rn(v.y)) << 16);
        uint32_t b = (uint32_t)__half_as_ushort(__float2half_rn(v.z)) |
                     ((uint32_t)__half_as_ushort(__float2half_rn(v.w)) << 16);
        ((uint2*)g_Xf)[i] = make_uint2(a, b);
    }
    for (size_t i = i0; i < NW4; i += stride) {
        float4 v = ((const float4*)W)[i];
        uint32_t a = (uint32_t)__half_as_ushort(__float2half_rn(v.x)) |
                     ((uint32_t)__half_as_ushort(__float2half_rn(v.y)) << 16);
        uint32_t b = (uint32_t)__half_as_ushort(__float2half_rn(v.z)) |
                     ((uint32_t)__half_as_ushort(__float2half_rn(v.w)) << 16);
        ((uint2*)g_Wf)[i] = make_uint2(a, b);
    }
    for (size_t i = i0; i < G4; i += stride) g_bias[i] = b1[i] + b2[i];
    for (size_t i = i0; i < 128; i += stride) g_syncg[i] = 0u;
}

// ---------------------------------------------------------------------------
// sgemm_f16: g_xg[t][n][b] = sum_k X[t][b][k] * W_ih[n][k] + bias[n]
// Single-pass f16 (lo stream removed from the validated winner).
// ---------------------------------------------------------------------------
#define STG_PITCH 132   // floats; 528B row, 16B aligned, conflict-free

__global__ void __launch_bounds__(256) sgemm_f16()
{
    __shared__ __align__(16) char SMEM[33792];   // tiles (20KB) / staging (33KB)
    __half* Ah = (__half*)(SMEM);
    __half* Bh = (__half*)(SMEM + 10240);

    const int t    = threadIdx.x;
    const int lane = t & 31;
    const int w    = t >> 5;
    const int wm   = w >> 1;
    const int wn   = w & 1;
    const int tt   = blockIdx.y;
    const int m0   = tt * 128;
    const int n0   = blockIdx.x * 128;

    const int row0 = t >> 2;
    const int grp  = t & 3;
    size_t ao0 = (size_t)(m0 + row0) * II + grp * 8;
    size_t ao1 = ao0 + (size_t)64 * II;
    size_t bo0 = (size_t)(n0 + row0) * II + grp * 8;
    size_t bo1 = bo0 + (size_t)64 * II;
    const int s0 = row0 * 40 + grp * 8;
    const int s1 = s0 + 64 * 40;

    const uint32_t uAh = smem_u32(Ah);
    const uint32_t uBh = smem_u32(Bh);
    const int a_r = lane & 15, a_c = (lane >> 4) << 3;
    const int b_r = lane & 7,  b_c = ((lane >> 3) & 1) << 3;

    float d[2][8][4] = {{{0.f}}};

    uint4 pAh0 = *(const uint4*)(g_Xf + ao0);
    uint4 pAh1 = *(const uint4*)(g_Xf + ao1);
    uint4 pBh0 = *(const uint4*)(g_Wf + bo0);
    uint4 pBh1 = *(const uint4*)(g_Wf + bo1);

    for (int it = 0; it < 16; ++it) {
        __syncthreads();
        *(uint4*)(Ah + s0) = pAh0; *(uint4*)(Ah + s1) = pAh1;
        *(uint4*)(Bh + s0) = pBh0; *(uint4*)(Bh + s1) = pBh1;
        __syncthreads();

        if (it != 15) {
            ao0 += 32; ao1 += 32; bo0 += 32; bo1 += 32;
            pAh0 = *(const uint4*)(g_Xf + ao0);
            pAh1 = *(const uint4*)(g_Xf + ao1);
            pBh0 = *(const uint4*)(g_Wf + bo0);
            pBh1 = *(const uint4*)(g_Wf + bo1);
        }

#pragma unroll
        for (int ks = 0; ks < 2; ++ks) {
            uint32_t ah[2][4];
#pragma unroll
            for (int mt = 0; mt < 2; ++mt) {
                uint32_t ra = uAh + (uint32_t)(((wm * 32 + mt * 16 + a_r) * 40 + ks * 16 + a_c) * 2);
                ldmx4(ah[mt][0], ah[mt][1], ah[mt][2], ah[mt][3], ra);
            }
#pragma unroll
            for (int nt = 0; nt < 8; ++nt) {
                uint32_t bh[2];
                uint32_t rb = uBh + (uint32_t)(((wn * 64 + nt * 8 + b_r) * 40 + ks * 16 + b_c) * 2);
                ldmx2(bh[0], bh[1], rb);
#pragma unroll
                for (int mt = 0; mt < 2; ++mt) {
                    mma_f16(d[mt][nt], ah[mt], bh);
                }
            }
        }
    }

    // Epilogue: two halves of 64 n-cols; transpose via smem, coalesced store.
    float* staging = (float*)SMEM;
    const int gid = lane >> 2, tig = lane & 3;
#pragma unroll
    for (int nh = 0; nh < 2; ++nh) {
        __syncthreads();
        if (wn == nh) {
#pragma unroll
            for (int mt = 0; mt < 2; ++mt)
#pragma unroll
                for (int nt = 0; nt < 8; ++nt) {
                    int c = nt * 8 + 2 * tig;            // local col in half
                    int r = wm * 32 + mt * 16 + gid;     // batch row
                    staging[c * STG_PITCH + r]           = d[mt][nt][0];
                    staging[(c + 1) * STG_PITCH + r]     = d[mt][nt][1];
                    staging[c * STG_PITCH + r + 8]       = d[mt][nt][2];
                    staging[(c + 1) * STG_PITCH + r + 8] = d[mt][nt][3];
                }
        }
        __syncthreads();
#pragma unroll
        for (int j = 0; j < 8; ++j) {
            int idx = t + 256 * j;            // 2048 float4 = 64 cols x 32 segs
            int col = idx >> 5, seg = idx & 31;
            int n = n0 + nh * 64 + col;
            float bb = g_bias[n];
            const float* sp = &staging[col * STG_PITCH + seg * 4];
            float4 v = make_float4(sp[0] + bb, sp[1] + bb, sp[2] + bb, sp[3] + bb);
            *(float4*)&g_xg[((size_t)tt * G4 + n) * BB + seg * 4] = v;
        }
    }
}

// ---------------------------------------------------------------------------
// Persistent recurrent kernel — round-13 winner with the W_lo stream removed
// (single-pass f16 W). 2D tiling: 32 h-col groups x 4 batch groups.
// ---------------------------------------------------------------------------
#define RW_PITCH 520
#define RS_WSH 0
#define RS_HS  66560
#define RS_CS  99840
#define RS_HST 108288
#define RS_TOT 110592

__global__ void __launch_bounds__(256, 1) lstm_rec(const float* __restrict__ Whh,
                                                   float* __restrict__ out,
                                                   int tail)
{
    extern __shared__ __align__(16) char rsm[];
    __half* Wsh = (__half*)(rsm + RS_WSH);
    float*  Cs  = (float*)(rsm + RS_CS);      // [64 col][33] transposed
    float* hstage = (float*)(rsm + RS_HST);   // [32 b][17]
    const uint32_t uSM = smem_u32(rsm);

    const int tid  = threadIdx.x;
    const int lane = tid & 31;
    const int w    = tid >> 5;
    const int gid  = lane >> 2;
    const int tig  = lane & 3;
    const int gh   = blockIdx.x & 31;   // h-col group
    const int gb   = blockIdx.x >> 5;   // batch group (independent recurrence)
    const int hc0  = gh * 16;
    const int b0   = gb * 32;
    volatile unsigned* mybar = &g_syncg[gb * 32];

    // Load W_hh slice (f16): Ws[j][k] = Whh[(j>>4)*512 + hc0 + (j&15)][k]
    for (int idx = tid; idx < 64 * 512; idx += 256) {
        int j = idx >> 9, k = idx & 511;
        int n = (j >> 4) * 512 + hc0 + (j & 15);
        Wsh[j * RW_PITCH + k] = __float2half_rn(Whh[(size_t)n * HH + k]);
    }
    __syncthreads();

    const int wm  = w & 1;              // m-tile (16 batches)
    const int wn  = w >> 1;             // n-group (16 gate cols)
    const int a_r = lane & 15, a_c = (lane >> 4) << 3;
    // B ldmatrix.x4 lane mapping: m0=nt0/k0-7, m1=nt0/k8-15, m2=nt1/k0-7, m3=nt1/k8-15
    const int b_nrow = wn * 16 + ((lane >> 4) << 3) + (lane & 7);
    const int b_koff = ((lane >> 3) & 1) << 3;
    const int e_b = tid & 31;           // local batch
    const int e_r = tid >> 5;           // ci base (handles ci = e_r, e_r+8)
    float creg[2] = {0.f, 0.f};

    // prologue: prefetch gates for t=0
    float xv[2][4];
#pragma unroll
    for (int pi = 0; pi < 2; ++pi) {
        int ci = e_r + pi * 8;
#pragma unroll
        for (int q = 0; q < 4; ++q)
            xv[pi][q] = g_xg[(size_t)(q * 512 + hc0 + ci) * BB + b0 + e_b];
    }

    for (int t = 0; t < TT; ++t) {
        if (t > 0) {
            // load h slice: 32 rows x 512 f16 = 2048 uint4, one shot
            const __half* srcH = g_Hf[(t - 1) & 1];
#pragma unroll
            for (int j = 0; j < 8; ++j) {
                int idx = tid + 256 * j;
                int row = idx >> 6, seg = idx & 63;
                *(uint4*)(rsm + RS_HS + (row * RW_PITCH + seg * 8) * 2) =
                    *(const uint4*)(srcH + (size_t)(b0 + row) * HH + seg * 8);
            }
            __syncthreads();

            float d[2][4] = {{0.f, 0.f, 0.f, 0.f}};
#pragma unroll 4
            for (int kk = 0; kk < 32; ++kk) {
                const int kb = kk * 16;
                uint32_t ah[4];
                uint32_t aoff = (uint32_t)(((wm * 16 + a_r) * RW_PITCH + kb + a_c) * 2);
                ldmx4(ah[0], ah[1], ah[2], ah[3], uSM + RS_HS + aoff);

                uint32_t boff = (uint32_t)((b_nrow * RW_PITCH + kb + b_koff) * 2);
                uint32_t bh4[4];
                ldmx4(bh4[0], bh4[1], bh4[2], bh4[3], uSM + RS_WSH + boff);
                mma_f16(d[0], ah, bh4 + 0);
                mma_f16(d[1], ah, bh4 + 2);
            }

            // dump C fragments transposed: Cs[col][b]
            const int arow = wm * 16 + gid;
#pragma unroll
            for (int nt = 0; nt < 2; ++nt) {
                int c0 = wn * 16 + nt * 8 + 2 * tig;
                Cs[c0 * 33 + arow]           = d[nt][0];
                Cs[(c0 + 1) * 33 + arow]     = d[nt][1];
                Cs[c0 * 33 + arow + 8]       = d[nt][2];
                Cs[(c0 + 1) * 33 + arow + 8] = d[nt][3];
            }
        }
        __syncthreads();

        // Fused fp32 LSTM elementwise -> h to smem stage
#pragma unroll
        for (int pi = 0; pi < 2; ++pi) {
            int ci = e_r + pi * 8;
            float gate[4];
#pragma unroll
            for (int q = 0; q < 4; ++q) {
                float s = (t > 0) ? Cs[(q * 16 + ci) * 33 + e_b] : 0.f;
                gate[q] = s + xv[pi][q];
            }
            float ig = 1.0f / (1.0f + __expf(-gate[0]));
            float fg = 1.0f / (1.0f + __expf(-gate[1]));
            float gg = tanhf(gate[2]);
            float og = 1.0f / (1.0f + __expf(-gate[3]));
            float cn = fg * creg[pi] + ig * gg;
            creg[pi] = cn;
            hstage[e_b * 17 + ci] = og * tanhf(cn);
        }
        __syncthreads();

        // coalesced h writes: float4 out + uint2 f16 h (4 cols per thread)
        if (tid < 128) {
            int bl_ = tid >> 2, qd = tid & 3;
            const float* hp = &hstage[bl_ * 17 + qd * 4];
            float h0 = hp[0], h1 = hp[1], h2 = hp[2], h3 = hp[3];
            *(float4*)(out + (size_t)t * BB * HH + (size_t)(b0 + bl_) * HH + hc0 + qd * 4) =
                make_float4(h0, h1, h2, h3);
            uint32_t p0 = (uint32_t)__half_as_ushort(__float2half_rn(h0)) |
                          ((uint32_t)__half_as_ushort(__float2half_rn(h1)) << 16);
            uint32_t p1 = (uint32_t)__half_as_ushort(__float2half_rn(h2)) |
                          ((uint32_t)__half_as_ushort(__float2half_rn(h3)) << 16);
            *(uint2*)(g_Hf[t & 1] + (size_t)(b0 + bl_) * HH + hc0 + qd * 4) =
                make_uint2(p0, p1);
        }

        // prefetch next step's gates BEFORE the barrier (hidden in the wait)
        if (t + 1 < TT) {
            const float* xgn = g_xg + (size_t)(t + 1) * G4 * BB;
#pragma unroll
            for (int pi = 0; pi < 2; ++pi) {
                int ci = e_r + pi * 8;
#pragma unroll
                for (int q = 0; q < 4; ++q)
                    xv[pi][q] = xgn[(size_t)(q * 512 + hc0 + ci) * BB + b0 + e_b];
            }
        }

        // per-group barrier (only the 32 same-gb blocks interact)
        __syncthreads();
        if (tid == 0) {
            __threadfence();
            atomicAdd((unsigned*)mybar, 1u);
            unsigned target = (unsigned)(t + 1) * 32u;
            while (*mybar < target) { }
            __threadfence();
        }
        __syncthreads();
    }

    // tail: hT copy + cT from registers
    if (tail) {
#pragma unroll
        for (int pi = 0; pi < 2; ++pi) {
            int ci = e_r + pi * 8;
            size_t idx = (size_t)(b0 + e_b) * HH + hc0 + ci;
            out[TBH + idx]           = out[(size_t)(TT - 1) * BB * HH + idx];
            out[TBH + BB * HH + idx] = creg[pi];
        }
    }
}

// ---------------------------------------------------------------------------
extern "C" void kernel_launch(void* const* d_in, const int* in_sizes, int n_in,
                              void* d_out, int out_size)
{
    const float* input = (const float*)d_in[0];
    /* d_in[1] = time, unused by the base cell */
    const float* W_ih  = (const float*)d_in[2];
    const float* W_hh  = (const float*)d_in[3];
    const float* b_ih  = (const float*)d_in[4];
    const float* b_hh  = (const float*)d_in[5];
    float* out = (float*)d_out;

    int tail = ((size_t)out_size >= TBH + 2ull * BB * HH) ? 1 : 0;

    convert_init<<<2048, 256>>>(input, W_ih, b_ih, b_hh);
    sgemm_f16<<<dim3(16, 512), 256>>>();

    cudaFuncSetAttribute(lstm_rec, cudaFuncAttributeMaxDynamicSharedMemorySize, RS_TOT);
    lstm_rec<<<NBLK, 256, RS_TOT>>>(W_hh, out, tail);
}